// round 6
// baseline (speedup 1.0000x reference)
#include <cuda_runtime.h>
#include <math.h>
#include <stdint.h>

#define NE   64
#define TK   8
#define DIM  2048
#define TM   128            // tokens per CTA
#define KC   64             // bf16 k per chunk
#define NCH  (DIM / KC)     // 32 chunks
#define SW   36             // smem row stride in 32-bit words (32 data + 4 pad)

// plane sizes / stage offsets in words
#define APLANE (TM * SW)                 // 4608
#define BPLANE (NE * SW)                 // 2304
#define AH_O 0
#define AM_O APLANE
#define AL_O (2 * APLANE)
#define BH_O (3 * APLANE)
#define BM_O (3 * APLANE + BPLANE)
#define BL_O (3 * APLANE + 2 * BPLANE)
#define STG_W (3 * APLANE + 3 * BPLANE)  // 20736 words = 82944 B
#define DYN_BYTES (2 * STG_W * 4)        // 165888 B
#define LS_STRIDE 68

__device__ __align__(16) uint16_t g_wh[NE * DIM];
__device__ __align__(16) uint16_t g_wm[NE * DIM];
__device__ __align__(16) uint16_t g_wl[NE * DIM];
__device__ __align__(16) float g_bias[NE];
__device__ float g_nbs;
__device__ float g_acc[NE];

static __device__ __forceinline__ uint32_t pack_bf16(float lo, float hi) {
    uint32_t r;
    asm("cvt.rn.bf16x2.f32 %0, %1, %2;" : "=r"(r) : "f"(hi), "f"(lo));
    return r;
}
static __device__ __forceinline__ float bf_lo(uint32_t p) { return __uint_as_float(p << 16); }
static __device__ __forceinline__ float bf_hi(uint32_t p) { return __uint_as_float(p & 0xFFFF0000u); }

static __device__ __forceinline__ void mma16(float* c,
    uint32_t a0, uint32_t a1, uint32_t a2, uint32_t a3, uint32_t b0, uint32_t b1)
{
    asm volatile(
        "mma.sync.aligned.m16n8k16.row.col.f32.bf16.bf16.f32 "
        "{%0,%1,%2,%3}, {%4,%5,%6,%7}, {%8,%9}, {%0,%1,%2,%3};"
        : "+f"(c[0]), "+f"(c[1]), "+f"(c[2]), "+f"(c[3])
        : "r"(a0), "r"(a1), "r"(a2), "r"(a3), "r"(b0), "r"(b1));
}

// 3-term bf16 split of a float4 -> packed (h01,h23,m01,m23,l01,l23)
static __device__ __forceinline__ void split3(float4 v,
    uint32_t& h01, uint32_t& h23, uint32_t& m01, uint32_t& m23,
    uint32_t& l01, uint32_t& l23)
{
    h01 = pack_bf16(v.x, v.y);
    h23 = pack_bf16(v.z, v.w);
    float rx = v.x - bf_lo(h01), ry = v.y - bf_hi(h01);
    float rz = v.z - bf_lo(h23), rw = v.w - bf_hi(h23);
    m01 = pack_bf16(rx, ry);
    m23 = pack_bf16(rz, rw);
    float sx = rx - bf_lo(m01), sy = ry - bf_hi(m01);
    float sz = rz - bf_lo(m23), sw = rw - bf_hi(m23);
    l01 = pack_bf16(sx, sy);
    l23 = pack_bf16(sz, sw);
}

// ---------------------------------------------------------------------------
// Setup: 3-term split of W (blocks 0..63), adaptive bias (block 64)
// ---------------------------------------------------------------------------
__global__ void k_setup(const float* __restrict__ W,
                        const float* __restrict__ loads,
                        const float* __restrict__ bs)
{
    int b = blockIdx.x, tid = threadIdx.x;

    if (b < NE) {
        const float4* wr = (const float4*)(W + (size_t)b * DIM);
        uint32_t* wh = (uint32_t*)g_wh;
        uint32_t* wm = (uint32_t*)g_wm;
        uint32_t* wl = (uint32_t*)g_wl;
        #pragma unroll
        for (int u = 0; u < 2; u++) {
            int f = u * 256 + tid;
            uint32_t h01, h23, m01, m23, l01, l23;
            split3(wr[f], h01, h23, m01, m23, l01, l23);
            int idx = (b * DIM + f * 4) >> 1;
            wh[idx] = h01; wh[idx + 1] = h23;
            wm[idx] = m01; wm[idx + 1] = m23;
            wl[idx] = l01; wl[idx + 1] = l23;
        }
    } else {
        __shared__ float s[NE], s2[NE];
        if (tid < NE) s[tid] = loads[tid];
        __syncthreads();
        float sum = 0.f, q = 0.f;
        const float t = 1.0f / (float)NE;
        if (tid < NE) {
            #pragma unroll
            for (int i = 0; i < NE; i++) sum += s[i];
            sum = fmaxf(sum, 1e-8f);
            q = s[tid] / sum;
            s2[tid] = t * (logf(t) - logf(fmaxf(q, 1e-8f)));
        }
        __syncthreads();
        if (tid < NE) {
            float kl = 0.f;
            #pragma unroll
            for (int i = 0; i < NE; i++) kl += s2[i];
            float adaptive = 1.0f / (1.0f + expf(-10.0f * kl));
            float nbs = 0.9f * bs[0] + 0.1f * adaptive;
            g_bias[tid] = tanhf((q - t) * (float)NE) * nbs;
            g_acc[tid] = 0.f;
            if (tid == 0) g_nbs = nbs;
        }
    }
}

// ---------------------------------------------------------------------------
// Router: bf16 3-term / 6-product mma.sync GEMM + fused epilogue
// warp w: h2 = w&3 -> token quarter (32 tokens), ksw = w>>2 -> k32 half of chunk
// ---------------------------------------------------------------------------
__global__ __launch_bounds__(256, 1) void k_router(
    const float* __restrict__ X,      // [ntok, DIM]
    const float* __restrict__ noise,  // [ntok, NE]
    float* __restrict__ out,
    int ntok)
{
    extern __shared__ __align__(16) char dsm[];
    __shared__ float sLoads[NE];
    __shared__ float sBias[NE];

    const int tid  = threadIdx.x;
    const int lane = tid & 31;
    const int warp = tid >> 5;
    const int h2   = warp & 3;       // token quarter
    const int ksw  = warp >> 2;      // k half within chunk (0/1)
    const int g    = lane >> 2;
    const int tig  = lane & 3;
    const int t0   = blockIdx.x * TM;

    if (tid < NE) { sLoads[tid] = 0.f; sBias[tid] = g_bias[tid]; }

    // fill indices
    const int ft = tid >> 1;         // token 0..127
    const int fh = tid & 1;          // k half (32 fp32 each)
    const int fe = tid >> 2;         // expert 0..63
    const int fq = tid & 3;          // 16-bf16 quarter of the row

    float acc[2][8][4];
    #pragma unroll
    for (int i = 0; i < 2; i++)
        #pragma unroll
        for (int j = 0; j < 8; j++)
            #pragma unroll
            for (int q = 0; q < 4; q++) acc[i][j][q] = 0.f;

    float4 xr[8];
    uint4  wvh[2], wvm[2], wvl[2];

    // ---- prefetch chunk 0 ----
    {
        const float* xp = X + (size_t)(t0 + ft) * DIM + fh * 32;
        #pragma unroll
        for (int u = 0; u < 8; u++) xr[u] = *(const float4*)(xp + u * 4);
        const uint4* ph = (const uint4*)(g_wh + (size_t)fe * DIM + fq * 16);
        const uint4* pm = (const uint4*)(g_wm + (size_t)fe * DIM + fq * 16);
        const uint4* pl = (const uint4*)(g_wl + (size_t)fe * DIM + fq * 16);
        wvh[0] = ph[0]; wvh[1] = ph[1];
        wvm[0] = pm[0]; wvm[1] = pm[1];
        wvl[0] = pl[0]; wvl[1] = pl[1];
    }
    // ---- convert + store chunk 0 into stage 0 ----
    {
        uint32_t* sw = (uint32_t*)dsm;
        int wb = ft * SW + fh * 16;
        #pragma unroll
        for (int u = 0; u < 8; u++) {
            uint32_t h01, h23, m01, m23, l01, l23;
            split3(xr[u], h01, h23, m01, m23, l01, l23);
            *(uint2*)&sw[AH_O + wb + u * 2] = make_uint2(h01, h23);
            *(uint2*)&sw[AM_O + wb + u * 2] = make_uint2(m01, m23);
            *(uint2*)&sw[AL_O + wb + u * 2] = make_uint2(l01, l23);
        }
        uint4* sb = (uint4*)dsm;
        int wq = fe * 9 + fq * 2;    // uint4 index within plane (36 words = 9 uint4)
        ((uint4*)&sw[BH_O])[wq] = wvh[0]; ((uint4*)&sw[BH_O])[wq + 1] = wvh[1];
        ((uint4*)&sw[BM_O])[wq] = wvm[0]; ((uint4*)&sw[BM_O])[wq + 1] = wvm[1];
        ((uint4*)&sw[BL_O])[wq] = wvl[0]; ((uint4*)&sw[BL_O])[wq + 1] = wvl[1];
        (void)sb;
    }
    __syncthreads();

    // ---- mainloop ----
    for (int c = 0; c < NCH; ++c) {
        const bool more = (c + 1 < NCH);
        if (more) {
            int kb = (c + 1) * KC;
            const float* xp = X + (size_t)(t0 + ft) * DIM + kb + fh * 32;
            #pragma unroll
            for (int u = 0; u < 8; u++) xr[u] = *(const float4*)(xp + u * 4);
            const uint4* ph = (const uint4*)(g_wh + (size_t)fe * DIM + kb + fq * 16);
            const uint4* pm = (const uint4*)(g_wm + (size_t)fe * DIM + kb + fq * 16);
            const uint4* pl = (const uint4*)(g_wl + (size_t)fe * DIM + kb + fq * 16);
            wvh[0] = ph[0]; wvh[1] = ph[1];
            wvm[0] = pm[0]; wvm[1] = pm[1];
            wvl[0] = pl[0]; wvl[1] = pl[1];
        }

        // ---- consume stage c&1 ----
        {
            const uint32_t* sw = (const uint32_t*)(dsm + (c & 1) * STG_W * 4);
            const uint32_t* ah = sw + AH_O;
            const uint32_t* am = sw + AM_O;
            const uint32_t* al = sw + AL_O;
            const uint32_t* bh = sw + BH_O;
            const uint32_t* bm = sw + BM_O;
            const uint32_t* bl = sw + BL_O;

            #pragma unroll
            for (int kk = 0; kk < 2; kk++) {
                const int k0 = ksw * 16 + kk * 8;

                uint32_t Bh[8][2], Bm[8][2], Bl[8][2];
                #pragma unroll
                for (int j = 0; j < 8; j++) {
                    int rb = (8 * j + g) * SW + k0 + tig;
                    Bh[j][0] = bh[rb]; Bh[j][1] = bh[rb + 4];
                    Bm[j][0] = bm[rb]; Bm[j][1] = bm[rb + 4];
                    Bl[j][0] = bl[rb]; Bl[j][1] = bl[rb + 4];
                }

                #pragma unroll
                for (int i = 0; i < 2; i++) {
                    int ra  = (32 * h2 + 16 * i + g) * SW + k0 + tig;
                    int ra8 = ra + 8 * SW;
                    uint32_t Ah0 = ah[ra],     Ah1 = ah[ra8];
                    uint32_t Ah2 = ah[ra + 4], Ah3 = ah[ra8 + 4];
                    uint32_t Am0 = am[ra],     Am1 = am[ra8];
                    uint32_t Am2 = am[ra + 4], Am3 = am[ra8 + 4];
                    uint32_t Al0 = al[ra],     Al1 = al[ra8];
                    uint32_t Al2 = al[ra + 4], Al3 = al[ra8 + 4];
                    #pragma unroll
                    for (int j = 0; j < 8; j++) {
                        mma16(acc[i][j], Ah0, Ah1, Ah2, Ah3, Bh[j][0], Bh[j][1]);
                        mma16(acc[i][j], Ah0, Ah1, Ah2, Ah3, Bm[j][0], Bm[j][1]);
                        mma16(acc[i][j], Am0, Am1, Am2, Am3, Bh[j][0], Bh[j][1]);
                        mma16(acc[i][j], Am0, Am1, Am2, Am3, Bm[j][0], Bm[j][1]);
                        mma16(acc[i][j], Ah0, Ah1, Ah2, Ah3, Bl[j][0], Bl[j][1]);
                        mma16(acc[i][j], Al0, Al1, Al2, Al3, Bh[j][0], Bh[j][1]);
                    }
                }
            }
        }

        // ---- convert + store chunk c+1 into the other stage ----
        if (more) {
            uint32_t* sw = (uint32_t*)(dsm + ((c + 1) & 1) * STG_W * 4);
            int wb = ft * SW + fh * 16;
            #pragma unroll
            for (int u = 0; u < 8; u++) {
                uint32_t h01, h23, m01, m23, l01, l23;
                split3(xr[u], h01, h23, m01, m23, l01, l23);
                *(uint2*)&sw[AH_O + wb + u * 2] = make_uint2(h01, h23);
                *(uint2*)&sw[AM_O + wb + u * 2] = make_uint2(m01, m23);
                *(uint2*)&sw[AL_O + wb + u * 2] = make_uint2(l01, l23);
            }
            int wq = fe * 9 + fq * 2;
            ((uint4*)&sw[BH_O])[wq] = wvh[0]; ((uint4*)&sw[BH_O])[wq + 1] = wvh[1];
            ((uint4*)&sw[BM_O])[wq] = wvm[0]; ((uint4*)&sw[BM_O])[wq + 1] = wvm[1];
            ((uint4*)&sw[BL_O])[wq] = wvl[0]; ((uint4*)&sw[BL_O])[wq + 1] = wvl[1];
            __syncthreads();
        }
    }
    __syncthreads();   // all MMA smem reads done before reuse

    // ---- cross-kstep reduction into logits tile Ls[128][68] ----
    float* Ls = (float*)dsm;
    for (int idx = tid; idx < TM * LS_STRIDE; idx += 256) Ls[idx] = 0.f;
    __syncthreads();

    for (int round = 0; round < 2; round++) {
        if (ksw == round) {
            #pragma unroll
            for (int i = 0; i < 2; i++) {
                int rt = 32 * h2 + 16 * i + g;
                #pragma unroll
                for (int j = 0; j < 8; j++) {
                    int cc = 8 * j + 2 * tig;
                    Ls[rt * LS_STRIDE + cc]           += acc[i][j][0];
                    Ls[rt * LS_STRIDE + cc + 1]       += acc[i][j][1];
                    Ls[(rt + 8) * LS_STRIDE + cc]     += acc[i][j][2];
                    Ls[(rt + 8) * LS_STRIDE + cc + 1] += acc[i][j][3];
                }
            }
        }
        __syncthreads();
    }

    // ---- epilogue: per-token top-8 + softmax + load scatter ----
    if (tid < TM) {
        const int t = tid;
        size_t gt = (size_t)(t0 + t);

        float nzf[NE];
        const float4* nr = (const float4*)(noise + gt * NE);
        #pragma unroll
        for (int i = 0; i < 16; i++) {
            float4 v = nr[i];
            nzf[4 * i + 0] = v.x; nzf[4 * i + 1] = v.y;
            nzf[4 * i + 2] = v.z; nzf[4 * i + 3] = v.w;
        }

        float tv[TK];
        int   ti_[TK];
        #pragma unroll
        for (int k = 0; k < TK; k++) { tv[k] = -INFINITY; ti_[k] = -1; }

        for (int e = 0; e < NE; e++) {
            float v = Ls[t * LS_STRIDE + e] + 0.01f * nzf[e] - sBias[e];
            if (v > tv[TK - 1]) {                 // strict >: earlier equal value stays
                int p = TK - 1;
                while (p > 0 && tv[p - 1] < v) {  // stop at equal -> stable insert
                    tv[p] = tv[p - 1];
                    ti_[p] = ti_[p - 1];
                    --p;
                }
                tv[p] = v;
                ti_[p] = e;
            }
        }

        float m = tv[0];
        float w[TK];
        float ssum = 0.f;
        #pragma unroll
        for (int k = 0; k < TK; k++) { w[k] = expf(tv[k] - m); ssum += w[k]; }
        float inv = 1.0f / ssum;

        size_t woff = (size_t)ntok * TK;
        #pragma unroll
        for (int k = 0; k < TK; k++) {
            float wk = w[k] * inv;
            out[gt * TK + k]        = (float)ti_[k];
            out[woff + gt * TK + k] = wk;
            atomicAdd(&sLoads[ti_[k]], wk);
        }
    }
    __syncthreads();
    if (tid < NE) atomicAdd(&g_acc[tid], sLoads[tid]);
}

// ---------------------------------------------------------------------------
// Final: EMA load update + new bias strength
// ---------------------------------------------------------------------------
__global__ void k_final(const float* __restrict__ loads, float* __restrict__ out, int ntok)
{
    int e = threadIdx.x;
    size_t base = (size_t)ntok * TK * 2;
    float batch = g_acc[e] / (float)ntok;
    out[base + e] = 0.999f * loads[e] + (1.0f - 0.999f) * batch;
    if (e == 0) out[base + NE] = g_nbs;
}

// ---------------------------------------------------------------------------
// Launch
// ---------------------------------------------------------------------------
extern "C" void kernel_launch(void* const* d_in, const int* in_sizes, int n_in,
                              void* d_out, int out_size)
{
    const float* X     = (const float*)d_in[0];  // hidden_states [4,4096,2048]
    const float* W     = (const float*)d_in[1];  // router_w [64,2048]
    const float* loads = (const float*)d_in[2];  // expert_loads [64]
    const float* bs    = (const float*)d_in[3];  // bias_strength [1]
    const float* noise = (const float*)d_in[4];  // noise [16384,64]
    float* out = (float*)d_out;

    int ntok = in_sizes[0] / DIM;

    cudaFuncSetAttribute(k_router, cudaFuncAttributeMaxDynamicSharedMemorySize, DYN_BYTES);

    k_setup<<<NE + 1, 256>>>(W, loads, bs);
    k_router<<<ntok / TM, 256, DYN_BYTES>>>(X, noise, out, ntok);
    k_final<<<1, NE>>>(loads, out, ntok);
}

// round 7
// speedup vs baseline: 1.2579x; 1.2579x over previous
#include <cuda_runtime.h>
#include <math.h>
#include <stdint.h>

#define NE   64
#define TK   8
#define DIM  2048
#define TM   128            // tokens per CTA
#define KB   32             // fp32 k per chunk
#define NCH  (DIM / KB)     // 64 chunks
#define RS   36             // smem row stride in words (32 data + 4 pad) -> conflict-free frags
#define NTH  512

// plane offsets per stage (words)
#define APL (TM * RS)            // 4608
#define BPL (NE * RS)            // 2304
#define AH_O 0
#define AL_O APL
#define BH_O (2 * APL)
#define BL_O (2 * APL + BPL)
#define STG_W (2 * APL + 2 * BPL)     // 13824 words = 55296 B
#define DYN_BYTES (2 * STG_W * 4)     // 110592 B
#define LS_STRIDE 68

__device__ __align__(16) float g_whi[NE * DIM];
__device__ __align__(16) float g_wlo[NE * DIM];
__device__ __align__(16) float g_bias[NE];
__device__ float g_nbs;
__device__ float g_acc[NE];

static __device__ __forceinline__ float fhi(float x) {
    return __uint_as_float(__float_as_uint(x) & 0xFFFFE000u);
}

static __device__ __forceinline__ void mma8(float* c,
    uint32_t a0, uint32_t a1, uint32_t a2, uint32_t a3, uint32_t b0, uint32_t b1)
{
    asm volatile(
        "mma.sync.aligned.m16n8k8.row.col.f32.tf32.tf32.f32 "
        "{%0,%1,%2,%3}, {%4,%5,%6,%7}, {%8,%9}, {%0,%1,%2,%3};"
        : "+f"(c[0]), "+f"(c[1]), "+f"(c[2]), "+f"(c[3])
        : "r"(a0), "r"(a1), "r"(a2), "r"(a3), "r"(b0), "r"(b1));
}

static __device__ __forceinline__ void cpa16(uint32_t dst, const void* src) {
    asm volatile("cp.async.ca.shared.global [%0], [%1], 16;"
                 :: "r"(dst), "l"(src) : "memory");
}

// ---------------------------------------------------------------------------
// Setup: split W into tf32 hi/lo fp32 planes (blocks 0..63), bias (block 64)
// ---------------------------------------------------------------------------
__global__ void k_setup(const float* __restrict__ W,
                        const float* __restrict__ loads,
                        const float* __restrict__ bs)
{
    int b = blockIdx.x, tid = threadIdx.x;

    if (b < NE) {
        const float4* wr = (const float4*)(W + (size_t)b * DIM);
        float4* whi = (float4*)(g_whi + (size_t)b * DIM);
        float4* wlo = (float4*)(g_wlo + (size_t)b * DIM);
        #pragma unroll
        for (int u = 0; u < 2; u++) {
            int f = u * 256 + tid;
            float4 v = wr[f];
            float4 h, l;
            h.x = fhi(v.x); h.y = fhi(v.y); h.z = fhi(v.z); h.w = fhi(v.w);
            l.x = v.x - h.x; l.y = v.y - h.y; l.z = v.z - h.z; l.w = v.w - h.w;
            whi[f] = h;
            wlo[f] = l;
        }
    } else {
        __shared__ float s[NE], s2[NE];
        if (tid < NE) s[tid] = loads[tid];
        __syncthreads();
        float sum = 0.f, q = 0.f;
        const float t = 1.0f / (float)NE;
        if (tid < NE) {
            #pragma unroll
            for (int i = 0; i < NE; i++) sum += s[i];
            sum = fmaxf(sum, 1e-8f);
            q = s[tid] / sum;
            s2[tid] = t * (logf(t) - logf(fmaxf(q, 1e-8f)));
        }
        __syncthreads();
        if (tid < NE) {
            float kl = 0.f;
            #pragma unroll
            for (int i = 0; i < NE; i++) kl += s2[i];
            float adaptive = 1.0f / (1.0f + expf(-10.0f * kl));
            float nbs = 0.9f * bs[0] + 0.1f * adaptive;
            g_bias[tid] = tanhf((q - t) * (float)NE) * nbs;
            g_acc[tid] = 0.f;
            if (tid == 0) g_nbs = nbs;
        }
    }
}

// ---------------------------------------------------------------------------
// Router: 3xTF32 mma8 GEMM, 512 threads
// warp w (0..15): h2 = w&3 -> 32-token quarter, ksw = w>>2 -> k8 slice of chunk
// ---------------------------------------------------------------------------
__global__ __launch_bounds__(NTH, 1) void k_router(
    const float* __restrict__ X,      // [ntok, DIM]
    const float* __restrict__ noise,  // [ntok, NE]
    float* __restrict__ out,
    int ntok)
{
    extern __shared__ __align__(16) float smem[];
    __shared__ float sLoads[NE];
    __shared__ float sBias[NE];

    const int tid  = threadIdx.x;
    const int lane = tid & 31;
    const int warp = tid >> 5;
    const int h2   = warp & 3;       // token quarter
    const int ksw  = warp >> 2;      // k8 slice (0..3)
    const int g    = lane >> 2;
    const int tig  = lane & 3;
    const int t0   = blockIdx.x * TM;

    if (tid < NE) { sLoads[tid] = 0.f; sBias[tid] = g_bias[tid]; }

    const uint32_t smem32 = (uint32_t)__cvta_generic_to_shared(smem);

    // fill indices: X -> 2 float4/thread ; B -> 1 hi + 1 lo cp.async/thread
    const int ft = tid >> 3;            // X token for u*512+tid... recomputed per u
    const int fe = tid >> 3;            // B expert 0..63
    const int fq = tid & 7;             // float4 index within 32-fp32 row
    (void)ft;

    float acc[2][8][4];
    #pragma unroll
    for (int i = 0; i < 2; i++)
        #pragma unroll
        for (int j = 0; j < 8; j++)
            #pragma unroll
            for (int q = 0; q < 4; q++) acc[i][j][q] = 0.f;

    float4 xr[2];

    // ---- fill chunk 0 into stage 0 ----
    {
        float* st = smem;
        #pragma unroll
        for (int u = 0; u < 2; u++) {
            int f = u * NTH + tid;
            int t = f >> 3, q = f & 7;
            float4 v = *(const float4*)(X + (size_t)(t0 + t) * DIM + q * 4);
            float4 h, l;
            h.x = fhi(v.x); h.y = fhi(v.y); h.z = fhi(v.z); h.w = fhi(v.w);
            l.x = v.x - h.x; l.y = v.y - h.y; l.z = v.z - h.z; l.w = v.w - h.w;
            *(float4*)&st[AH_O + t * RS + q * 4] = h;
            *(float4*)&st[AL_O + t * RS + q * 4] = l;
        }
        uint32_t bw = (uint32_t)((fe * RS + fq * 4) * 4);
        cpa16(smem32 + BH_O * 4 + bw, g_whi + (size_t)fe * DIM + fq * 4);
        cpa16(smem32 + BL_O * 4 + bw, g_wlo + (size_t)fe * DIM + fq * 4);
        asm volatile("cp.async.commit_group;" ::: "memory");
        asm volatile("cp.async.wait_group 0;" ::: "memory");
    }
    __syncthreads();

    // ---- mainloop ----
    for (int c = 0; c < NCH; ++c) {
        const bool more = (c + 1 < NCH);
        if (more) {
            int kb = (c + 1) * KB;
            #pragma unroll
            for (int u = 0; u < 2; u++) {
                int f = u * NTH + tid;
                xr[u] = *(const float4*)(X + (size_t)(t0 + (f >> 3)) * DIM + kb + (f & 7) * 4);
            }
            uint32_t sb = smem32 + (uint32_t)(((c + 1) & 1) * STG_W * 4);
            uint32_t bw = (uint32_t)((fe * RS + fq * 4) * 4);
            cpa16(sb + BH_O * 4 + bw, g_whi + (size_t)fe * DIM + kb + fq * 4);
            cpa16(sb + BL_O * 4 + bw, g_wlo + (size_t)fe * DIM + kb + fq * 4);
            asm volatile("cp.async.commit_group;" ::: "memory");
        }

        // ---- consume stage c&1 ----
        {
            const float* st = smem + (c & 1) * STG_W;
            const float* ah = st + AH_O;
            const float* al = st + AL_O;
            const float* bh = st + BH_O;
            const float* bl = st + BL_O;
            const int k0 = ksw * 8;

            // A fragments for both 16-row tiles (hi & lo)
            uint32_t Ah[2][4], Al[2][4];
            #pragma unroll
            for (int i = 0; i < 2; i++) {
                int ra  = (32 * h2 + 16 * i + g) * RS + k0 + tig;
                int ra8 = ra + 8 * RS;
                Ah[i][0] = __float_as_uint(ah[ra]);
                Ah[i][1] = __float_as_uint(ah[ra8]);
                Ah[i][2] = __float_as_uint(ah[ra + 4]);
                Ah[i][3] = __float_as_uint(ah[ra8 + 4]);
                Al[i][0] = __float_as_uint(al[ra]);
                Al[i][1] = __float_as_uint(al[ra8]);
                Al[i][2] = __float_as_uint(al[ra + 4]);
                Al[i][3] = __float_as_uint(al[ra8 + 4]);
            }

            #pragma unroll
            for (int j = 0; j < 8; j++) {
                int rb = (8 * j + g) * RS + k0;
                uint32_t Bh0 = __float_as_uint(bh[rb + tig]);
                uint32_t Bh1 = __float_as_uint(bh[rb + tig + 4]);
                uint32_t Bl0 = __float_as_uint(bl[rb + tig]);
                uint32_t Bl1 = __float_as_uint(bl[rb + tig + 4]);
                #pragma unroll
                for (int i = 0; i < 2; i++) {
                    mma8(acc[i][j], Ah[i][0], Ah[i][1], Ah[i][2], Ah[i][3], Bh0, Bh1);
                    mma8(acc[i][j], Ah[i][0], Ah[i][1], Ah[i][2], Ah[i][3], Bl0, Bl1);
                    mma8(acc[i][j], Al[i][0], Al[i][1], Al[i][2], Al[i][3], Bh0, Bh1);
                }
            }
        }

        // ---- store X(c+1) + drain B cp.async ----
        if (more) {
            float* st = smem + ((c + 1) & 1) * STG_W;
            #pragma unroll
            for (int u = 0; u < 2; u++) {
                int f = u * NTH + tid;
                int t = f >> 3, q = f & 7;
                float4 v = xr[u];
                float4 h, l;
                h.x = fhi(v.x); h.y = fhi(v.y); h.z = fhi(v.z); h.w = fhi(v.w);
                l.x = v.x - h.x; l.y = v.y - h.y; l.z = v.z - h.z; l.w = v.w - h.w;
                *(float4*)&st[AH_O + t * RS + q * 4] = h;
                *(float4*)&st[AL_O + t * RS + q * 4] = l;
            }
            asm volatile("cp.async.wait_group 0;" ::: "memory");
        }
        __syncthreads();
    }

    // ---- cross-kstep reduction into logits tile Ls[128][68] ----
    float* Ls = smem;
    for (int idx = tid; idx < TM * LS_STRIDE; idx += NTH) Ls[idx] = 0.f;
    __syncthreads();

    for (int round = 0; round < 4; round++) {
        if (ksw == round) {
            #pragma unroll
            for (int i = 0; i < 2; i++) {
                int rt = 32 * h2 + 16 * i + g;
                #pragma unroll
                for (int j = 0; j < 8; j++) {
                    int cc = 8 * j + 2 * tig;
                    Ls[rt * LS_STRIDE + cc]           += acc[i][j][0];
                    Ls[rt * LS_STRIDE + cc + 1]       += acc[i][j][1];
                    Ls[(rt + 8) * LS_STRIDE + cc]     += acc[i][j][2];
                    Ls[(rt + 8) * LS_STRIDE + cc + 1] += acc[i][j][3];
                }
            }
        }
        __syncthreads();
    }

    // ---- epilogue: per-token top-8 + softmax + load scatter ----
    if (tid < TM) {
        const int t = tid;
        size_t gt = (size_t)(t0 + t);

        float nzf[NE];
        const float4* nr = (const float4*)(noise + gt * NE);
        #pragma unroll
        for (int i = 0; i < 16; i++) {
            float4 v = nr[i];
            nzf[4 * i + 0] = v.x; nzf[4 * i + 1] = v.y;
            nzf[4 * i + 2] = v.z; nzf[4 * i + 3] = v.w;
        }

        float tv[TK];
        int   ti_[TK];
        #pragma unroll
        for (int k = 0; k < TK; k++) { tv[k] = -INFINITY; ti_[k] = -1; }

        for (int e = 0; e < NE; e++) {
            float v = Ls[t * LS_STRIDE + e] + 0.01f * nzf[e] - sBias[e];
            if (v > tv[TK - 1]) {                 // strict >: earlier equal value stays
                int p = TK - 1;
                while (p > 0 && tv[p - 1] < v) {  // stop at equal -> stable insert
                    tv[p] = tv[p - 1];
                    ti_[p] = ti_[p - 1];
                    --p;
                }
                tv[p] = v;
                ti_[p] = e;
            }
        }

        float m = tv[0];
        float w[TK];
        float ssum = 0.f;
        #pragma unroll
        for (int k = 0; k < TK; k++) { w[k] = expf(tv[k] - m); ssum += w[k]; }
        float inv = 1.0f / ssum;

        size_t woff = (size_t)ntok * TK;
        #pragma unroll
        for (int k = 0; k < TK; k++) {
            float wk = w[k] * inv;
            out[gt * TK + k]        = (float)ti_[k];
            out[woff + gt * TK + k] = wk;
            atomicAdd(&sLoads[ti_[k]], wk);
        }
    }
    __syncthreads();
    if (tid < NE) atomicAdd(&g_acc[tid], sLoads[tid]);
}

// ---------------------------------------------------------------------------
// Final: EMA load update + new bias strength
// ---------------------------------------------------------------------------
__global__ void k_final(const float* __restrict__ loads, float* __restrict__ out, int ntok)
{
    int e = threadIdx.x;
    size_t base = (size_t)ntok * TK * 2;
    float batch = g_acc[e] / (float)ntok;
    out[base + e] = 0.999f * loads[e] + (1.0f - 0.999f) * batch;
    if (e == 0) out[base + NE] = g_nbs;
}

// ---------------------------------------------------------------------------
// Launch
// ---------------------------------------------------------------------------
extern "C" void kernel_launch(void* const* d_in, const int* in_sizes, int n_in,
                              void* d_out, int out_size)
{
    const float* X     = (const float*)d_in[0];  // hidden_states [4,4096,2048]
    const float* W     = (const float*)d_in[1];  // router_w [64,2048]
    const float* loads = (const float*)d_in[2];  // expert_loads [64]
    const float* bs    = (const float*)d_in[3];  // bias_strength [1]
    const float* noise = (const float*)d_in[4];  // noise [16384,64]
    float* out = (float*)d_out;

    int ntok = in_sizes[0] / DIM;

    cudaFuncSetAttribute(k_router, cudaFuncAttributeMaxDynamicSharedMemorySize, DYN_BYTES);

    k_setup<<<NE + 1, 256>>>(W, loads, bs);
    k_router<<<ntok / TM, NTH, DYN_BYTES>>>(X, noise, out, ntok);
    k_final<<<1, NE>>>(loads, out, ntok);
}